// round 11
// baseline (speedup 1.0000x reference)
#include <cuda_runtime.h>
#include <cuda_bf16.h>
#include <cstdint>

// OutputLayer LIF step — algebraic identity: out = (v_reset > 0.5) where
// v_reset = v*(1-spike1). If v > thr, v resets to exactly 0; otherwise
// v <= thr and the final compare is strict. So out == 0 for ALL inputs;
// the minimal work is a 134MB zero-fill of d_out (poisoned to 0xAA).
//
// Optimization history (GB300, sm_103a):
//  R1: SM 16B stores            dur 23.14   (6.65 TB/s)
//  R2: SM 8x16B + .cs hint      NEUTRAL     (width/hint/grid insensitive)
//  R4: 134MB evict_last         31.2us      REGRESS (policy thrash)
//  R5: single CE memset node    dur 23.01   BEST
//  R6: 96MB evict_last split    27.4us      REGRESS (evict_last path slow
//                                           at any footprint)
//  R7: concurrent SM + CE       dur 24.06   => 6.65 TB/s is a SHARED
//                                           DRAM-write cap, not per-path
//  R8-R10: R5 re-bench          dur 23.008  reproduced exactly, 3x
//
// Converged model: floor = 134MB / 6.65TB/s (20.2us engine, ncu-confirmed
// on the SM path) + ~2.8us per-replay graph overhead = 23.0us. Byte count
// irreducible (full-buffer validation), L2 steady-state reuse unreachable
// (evict_last regresses monotonically; default policy scan-thrashes),
// multi-engine concurrency gains zero (shared DRAM ceiling). Single memset
// node is floor-optimal. FINAL — 23.008us, within 0.04% of modeled floor.

extern "C" void kernel_launch(void* const* d_in, const int* in_sizes, int n_in,
                              void* d_out, int out_size) {
    (void)d_in; (void)in_sizes; (void)n_in;

    size_t bytes = (size_t)out_size * sizeof(float);   // 134,217,728 bytes
    // Single memset node on the capture (default) stream: one graph node,
    // CE fill path, DRAM-write bound at the shared ~6.65 TB/s ceiling.
    cudaMemsetAsync(d_out, 0, bytes, 0);
}

// round 12
// speedup vs baseline: 1.0124x; 1.0124x over previous
#include <cuda_runtime.h>
#include <cuda_bf16.h>
#include <cstdint>

// OutputLayer LIF step — algebraic identity: out = (v_reset > 0.5) where
// v_reset = v*(1-spike1). If v > thr, v resets to exactly 0; otherwise
// v <= thr and the final compare is strict. So out == 0 for ALL inputs;
// the minimal work is a 134MB zero-fill of d_out (poisoned to 0xAA).
//
// Optimization history (GB300, sm_103a):
//  R1: SM 16B stores            dur 23.14   (6.65 TB/s)
//  R2: SM 8x16B + .cs hint      NEUTRAL     (width/hint/grid insensitive)
//  R4: 134MB evict_last         31.2us      REGRESS (policy thrash)
//  R5: single CE memset node    dur 23.01   BEST
//  R6: 96MB evict_last split    27.4us      REGRESS (evict_last path slow
//                                           at any footprint)
//  R7: concurrent SM + CE       dur 24.06   => 6.65 TB/s is a SHARED
//                                           DRAM-write cap, not per-path
//  R8-R10: re-bench             23.008 x3   (bit-identical)
//  R11: re-bench                23.552      first noise (+2.4%, within the
//                               documented LTS/clock run-to-run band)
//
// Converged model: floor = 134MB / ~6.6TB/s (20.2us engine, ncu-confirmed
// on the SM path) + ~2.8us per-replay graph overhead = ~23us. Byte count
// irreducible (full-buffer validation), L2 steady-state reuse unreachable
// (evict_last regresses monotonically; default policy scan-thrashes),
// multi-engine concurrency gains zero (shared DRAM ceiling). Single memset
// node is floor-optimal. FINAL.

extern "C" void kernel_launch(void* const* d_in, const int* in_sizes, int n_in,
                              void* d_out, int out_size) {
    (void)d_in; (void)in_sizes; (void)n_in;

    size_t bytes = (size_t)out_size * sizeof(float);   // 134,217,728 bytes
    // Single memset node on the capture (default) stream: one graph node,
    // CE fill path, DRAM-write bound at the shared ~6.6 TB/s ceiling.
    cudaMemsetAsync(d_out, 0, bytes, 0);
}

// round 13
// speedup vs baseline: 1.0138x; 1.0014x over previous
#include <cuda_runtime.h>
#include <cuda_bf16.h>
#include <cstdint>

// OutputLayer LIF step — algebraic identity: out = (v_reset > 0.5) where
// v_reset = v*(1-spike1). If v > thr, v resets to exactly 0; otherwise
// v <= thr and the final compare is strict. So out == 0 for ALL inputs;
// the minimal work is a 134MB zero-fill of d_out (poisoned to 0xAA).
//
// Optimization history (GB300, sm_103a):
//  R1: SM 16B stores            dur 23.14   (6.65 TB/s)
//  R2: SM 8x16B + .cs hint      NEUTRAL     (width/hint/grid insensitive)
//  R4: 134MB evict_last         31.2us      REGRESS (policy thrash)
//  R5: single CE memset node    dur 23.01   BEST
//  R6: 96MB evict_last split    27.4us      REGRESS (evict_last slow at
//                                           any footprint)
//  R7: concurrent SM + CE       dur 24.06   => shared DRAM-write cap
//  R8-R12: re-bench x5          23.008 x3, 23.552, 23.264 — ±1.5% noise
//                               band around the 23.0us floor
//
// Converged model: floor = 134MB / ~6.6TB/s (20.2us engine, ncu-confirmed
// on the SM path) + ~2.8us per-replay graph overhead = ~23us. Byte count
// irreducible (full-buffer validation), L2 steady-state reuse unreachable,
// multi-engine concurrency gains zero. Single memset node is floor-optimal.
// FINAL.

extern "C" void kernel_launch(void* const* d_in, const int* in_sizes, int n_in,
                              void* d_out, int out_size) {
    (void)d_in; (void)in_sizes; (void)n_in;

    size_t bytes = (size_t)out_size * sizeof(float);   // 134,217,728 bytes
    // Single memset node on the capture (default) stream: one graph node,
    // CE fill path, DRAM-write bound at the shared ~6.6 TB/s ceiling.
    cudaMemsetAsync(d_out, 0, bytes, 0);
}

// round 14
// speedup vs baseline: 1.0222x; 1.0083x over previous
#include <cuda_runtime.h>
#include <cuda_bf16.h>
#include <cstdint>

// OutputLayer LIF step — algebraic identity: out = (v_reset > 0.5) where
// v_reset = v*(1-spike1). If v > thr, v resets to exactly 0; otherwise
// v <= thr and the final compare is strict. So out == 0 for ALL inputs;
// the minimal work is a 134MB zero-fill of d_out (poisoned to 0xAA).
//
// Optimization history (GB300, sm_103a):
//  R1: SM 16B stores            dur 23.14   (6.65 TB/s)
//  R2: SM 8x16B + .cs hint      NEUTRAL     (width/hint/grid insensitive)
//  R4: 134MB evict_last         31.2us      REGRESS (policy thrash)
//  R5: single CE memset node    dur 23.01   BEST
//  R6: 96MB evict_last split    27.4us      REGRESS (evict_last slow at
//                                           any footprint)
//  R7: concurrent SM + CE       dur 24.06   => shared DRAM-write cap
//  R8-R13: re-bench x6          {23.008 x3, 23.232, 23.264, 23.552}
//                               ±1.5% noise band around the 23.0us floor
//
// Converged model: floor = 134MB / ~6.6TB/s (20.2us engine, ncu-confirmed
// on the SM path) + ~2.8us per-replay graph overhead = ~23us. Byte count
// irreducible (full-buffer validation), L2 steady-state reuse unreachable,
// multi-engine concurrency gains zero. Single memset node is floor-optimal.
// FINAL.

extern "C" void kernel_launch(void* const* d_in, const int* in_sizes, int n_in,
                              void* d_out, int out_size) {
    (void)d_in; (void)in_sizes; (void)n_in;

    size_t bytes = (size_t)out_size * sizeof(float);   // 134,217,728 bytes
    // Single memset node on the capture (default) stream: one graph node,
    // CE fill path, DRAM-write bound at the shared ~6.6 TB/s ceiling.
    cudaMemsetAsync(d_out, 0, bytes, 0);
}

// round 15
// speedup vs baseline: 1.0236x; 1.0014x over previous
#include <cuda_runtime.h>
#include <cuda_bf16.h>
#include <cstdint>

// OutputLayer LIF step — algebraic identity: out = (v_reset > 0.5) where
// v_reset = v*(1-spike1). If v > thr, v resets to exactly 0; otherwise
// v <= thr and the final compare is strict. So out == 0 for ALL inputs;
// the minimal work is a 134MB zero-fill of d_out (poisoned to 0xAA).
//
// Optimization history (GB300, sm_103a):
//  R1: SM 16B stores            dur 23.14   (6.65 TB/s)
//  R2: SM 8x16B + .cs hint      NEUTRAL     (width/hint/grid insensitive)
//  R4: 134MB evict_last         31.2us      REGRESS (policy thrash)
//  R5: single CE memset node    dur 23.01   BEST
//  R6: 96MB evict_last split    27.4us      REGRESS (evict_last slow at
//                                           any footprint)
//  R7: concurrent SM + CE       dur 24.06   => shared DRAM-write cap
//  R8-R14: re-bench x7          {23.008 x3, 23.040, 23.232, 23.264,
//                               23.552} — stable noise band at the floor
//
// Converged model: floor = 134MB / ~6.6TB/s (20.2us engine, ncu-confirmed
// on the SM path) + ~2.8us per-replay graph overhead = ~23us. Byte count
// irreducible (full-buffer validation), L2 steady-state reuse unreachable,
// multi-engine concurrency gains zero. Single memset node is floor-optimal.
// FINAL.

extern "C" void kernel_launch(void* const* d_in, const int* in_sizes, int n_in,
                              void* d_out, int out_size) {
    (void)d_in; (void)in_sizes; (void)n_in;

    size_t bytes = (size_t)out_size * sizeof(float);   // 134,217,728 bytes
    // Single memset node on the capture (default) stream: one graph node,
    // CE fill path, DRAM-write bound at the shared ~6.6 TB/s ceiling.
    cudaMemsetAsync(d_out, 0, bytes, 0);
}